// round 15
// baseline (speedup 1.0000x reference)
#include <cuda_runtime.h>
#include <cuda_bf16.h>
#include <cstdint>

// ============================================================================
// IsingRBM: psi[m] = prod_h cos(bias[h] + (x@W1)[m,h] + 0.5 * x^T W2[h] x)
// mma.sync.m16n8k16 bf16 (compute_103 baseline PTX; tcgen05 unavailable).
//
// R15 = R10 main kernel VERBATIM (best measured main: 33.2 us) + carveout
// alignment: prep now requests the SAME max dynamic-smem carveout as the
// main kernel (extern shared + attribute + launch bytes), eliminating the
// suspected L1/smem carveout reconfiguration between the two kernels that
// showed up as a 3-6 us total-minus-main gap in large-smem configs.
//
// Main (R10): 8-granular symmetric packing (K=2368, 37 chunks), compile-time
// schedule via constexpr half_desc, 512 thr / 1 CTA per SM, 4Mx4N warps,
// 8 cp.async B-buffers, barrier every 4 chunks.
// ============================================================================

static constexpr int kV = 64;
static constexpr int kH = 128;
static constexpr int kMTile = 128;
static constexpr int kChunks = 37;
static constexpr int kChunkBytes = kH * kV * 2;   // 16384
static constexpr int kThreads = 512;
static constexpr int kNBuf = 8;

// smem layout (bytes, relative to 1024-aligned base)
static constexpr int SM_BIAS = 0;                  // 128 f32 = 512
static constexpr int SM_PART = 512;                // 128*4 f32 = 2048
static constexpr int SM_XQ   = 2560;               // 64 j * 32 grp * 4 t u32 = 32768
static constexpr int SM_B    = 35840;              // 8 * 16384, 1024-aligned
static constexpr int SM_XT   = SM_B + 4 * kChunkBytes;      // overlay on buf 4
static constexpr int SM_END  = SM_B + kNBuf * kChunkBytes;  // 166912
static constexpr int SMEM_TOTAL = SM_END + 1024;   // 167936 < 227 KB

// Packed B operand: [chunk][h][64] bf16.
__device__ __align__(16) __nv_bfloat16 g_wb[kChunks * kH * kV];

// ---------------------------------------------------------------------------
// schedule: half H (octet of K) -> (row i, j-octet jo).  i == 64 => linear.
// Group a = i>>3 holds rows 8a..8a+7, each covering octets a..7.
// ---------------------------------------------------------------------------
struct HD { int i; int jo; };
__host__ __device__ constexpr HD half_desc(int H) {
    if (H >= 288) return HD{64, H - 288};          // linear term (scale = 1)
    int a = 0, gs = 0;
    while (gs + 8 * (8 - a) <= H) { gs += 8 * (8 - a); ++a; }
    int rem = H - gs, len = 8 - a;
    return HD{8 * a + rem / len, a + rem % len};
}

// ---------------------------------------------------------------------------
// helpers
// ---------------------------------------------------------------------------
__device__ __forceinline__ uint32_t smem_u32(const void* p) {
    uint32_t a;
    asm("{ .reg .u64 t; cvta.to.shared.u64 t, %1; cvt.u32.u64 %0, t; }"
        : "=r"(a) : "l"(p));
    return a;
}

#define SW128(o) ((o) ^ (((o) >> 3) & 0x70))

#define CVT_BF16X2(result, a, b) \
    asm("cvt.rn.bf16x2.f32 %0, %1, %2;" : "=r"(result) : "f"(b), "f"(a))

#define HMUL2(d, a, b) \
    asm("mul.rn.bf16x2 %0, %1, %2;" : "=r"(d) : "r"(a), "r"(b))

#define LDSM_X4(r0, r1, r2, r3, addr) \
    asm volatile("ldmatrix.sync.aligned.m8n8.x4.shared.b16 {%0,%1,%2,%3}, [%4];" \
        : "=r"(r0), "=r"(r1), "=r"(r2), "=r"(r3) : "r"(addr))

#define MMA16816(d, a0, a1, a2, a3, b0, b1) \
    asm volatile("mma.sync.aligned.m16n8k16.row.col.f32.bf16.bf16.f32 " \
        "{%0,%1,%2,%3}, {%4,%5,%6,%7}, {%8,%9}, {%0,%1,%2,%3};" \
        : "+f"((d)[0]), "+f"((d)[1]), "+f"((d)[2]), "+f"((d)[3]) \
        : "r"(a0), "r"(a1), "r"(a2), "r"(a3), "r"(b0), "r"(b1))

#define CP_ASYNC16(smem, gmem) \
    asm volatile("cp.async.cg.shared.global [%0], [%1], 16;" \
        :: "r"(smem), "l"(gmem) : "memory")
#define CP_COMMIT() asm volatile("cp.async.commit_group;" ::: "memory")
#define CP_WAIT4()  asm volatile("cp.async.wait_group 4;" ::: "memory")

__device__ __forceinline__ float cos_poly(float a) {
    // |a| < 0.1 guaranteed by problem statistics; deg-8 Taylor, err < 1e-12
    float t = a * a;
    return 1.0f + t * (-0.5f + t * (4.16666667e-2f +
               t * (-1.38888889e-3f + t * 2.48015873e-5f)));
}

// ---------------------------------------------------------------------------
// prep: one CTA per h. Stage W2[h] in smem (coalesced), emit the packed bf16
// row for every column of every chunk via half_desc.
// NOTE: sw is now DYNAMIC shared memory, and the launcher requests the same
// max dynamic-smem size as the main kernel, so both kernels run under one
// L1/smem carveout configuration (no inter-kernel reconfig).
// ---------------------------------------------------------------------------
__global__ void __launch_bounds__(256) prep_kernel(const float* __restrict__ w2,
                                                   const float* __restrict__ w1) {
    extern __shared__ float sw[];   // uses first 16 KB of the large allocation
    const int h = blockIdx.x;
    const float4* src = reinterpret_cast<const float4*>(w2 + (size_t)h * 4096);
    #pragma unroll
    for (int e = threadIdx.x; e < 1024; e += 256)
        reinterpret_cast<float4*>(sw)[e] = src[e];
    __syncthreads();

    // 37 chunks * 16 col-quads = 592 uint2 outputs for this h
    for (int idx = threadIdx.x; idx < kChunks * 16; idx += 256) {
        int c    = idx >> 4;
        int colq = (idx & 15) * 4;
        float v[4];
        #pragma unroll
        for (int q = 0; q < 4; q++) {
            int col = colq + q;
            HD hd = half_desc(c * 8 + (col >> 3));
            int j = hd.jo * 8 + (col & 7);
            if (hd.i == 64)     v[q] = 2.0f * w1[j * kH + h];
            else if (j > hd.i)  v[q] = sw[hd.i * 64 + j] + sw[j * 64 + hd.i];
            else if (j == hd.i) v[q] = sw[hd.i * 64 + j];
            else                v[q] = 0.0f;   // octet padding below diagonal
        }
        uint32_t lo, hi;
        CVT_BF16X2(lo, v[0], v[1]);
        CVT_BF16X2(hi, v[2], v[3]);
        reinterpret_cast<uint2*>(g_wb)[c * 2048 + h * 16 + (colq >> 2)] =
            make_uint2(lo, hi);
    }
}

// ---------------------------------------------------------------------------
// cp.async issue (2 x 16B per thread per chunk; 512 thr -> 16 KB)
// ---------------------------------------------------------------------------
__device__ __forceinline__ void issue_chunk(int c, uint32_t sb,
    const uint32_t (&cp_raw)[2], const uint32_t (&cp_dst)[2]) {
    const char* src = (const char*)g_wb + (size_t)c * kChunkBytes;
    uint32_t dst = sb + SM_B + (uint32_t)(c & 7) * kChunkBytes;
    CP_ASYNC16(dst + cp_dst[0], src + cp_raw[0]);
    CP_ASYNC16(dst + cp_dst[1], src + cp_raw[1]);
}

// ---------------------------------------------------------------------------
// one k16 block (KB) of chunk C: all schedule data compile-time.
// ab[mb][jo][0,1] = bf16x2 of x rows (wm+16mb+g, +8) at j = 8jo + 2*t4.
// xqg points at this thread's scale quadruple base; j-stride 128 u32.
// ---------------------------------------------------------------------------
template<int C, int KB>
__device__ __forceinline__ void do_kb(uint32_t bb, const uint32_t (&boff)[8],
    const uint32_t (&ab)[2][8][2], const uint32_t* __restrict__ xqg,
    float (&acc)[2][4][4])
{
    constexpr HD H0 = half_desc(C * 8 + KB * 2);
    constexpr HD H1 = half_desc(C * 8 + KB * 2 + 1);
    uint32_t sv0[4], sv1[4];
    if constexpr (H0.i == 64) {
        sv0[0] = sv0[1] = sv0[2] = sv0[3] = 0x3F803F80u;    // bf16x2(1,1)
    } else {
        uint4 s = *reinterpret_cast<const uint4*>(xqg + H0.i * 128);
        sv0[0] = s.x; sv0[1] = s.y; sv0[2] = s.z; sv0[3] = s.w;
    }
    if constexpr (H1.i == H0.i) {
        sv1[0] = sv0[0]; sv1[1] = sv0[1]; sv1[2] = sv0[2]; sv1[3] = sv0[3];
    } else if constexpr (H1.i == 64) {
        sv1[0] = sv1[1] = sv1[2] = sv1[3] = 0x3F803F80u;
    } else {
        uint4 s = *reinterpret_cast<const uint4*>(xqg + H1.i * 128);
        sv1[0] = s.x; sv1[1] = s.y; sv1[2] = s.z; sv1[3] = s.w;
    }
    uint32_t bf[4][2];
    LDSM_X4(bf[0][0], bf[0][1], bf[1][0], bf[1][1], bb + boff[KB * 2 + 0]);
    LDSM_X4(bf[2][0], bf[2][1], bf[3][0], bf[3][1], bb + boff[KB * 2 + 1]);
    #pragma unroll
    for (int mb = 0; mb < 2; mb++) {
        uint32_t t0, t1, t2, t3;
        HMUL2(t0, ab[mb][H0.jo][0], sv0[2 * mb]);      // rows g,   k 0-7
        HMUL2(t1, ab[mb][H0.jo][1], sv0[2 * mb + 1]);  // rows g+8, k 0-7
        HMUL2(t2, ab[mb][H1.jo][0], sv1[2 * mb]);      // rows g,   k 8-15
        HMUL2(t3, ab[mb][H1.jo][1], sv1[2 * mb + 1]);  // rows g+8, k 8-15
        #pragma unroll
        for (int nb = 0; nb < 4; nb++)
            MMA16816(acc[mb][nb], t0, t1, t2, t3, bf[nb][0], bf[nb][1]);
    }
}

// ---------------------------------------------------------------------------
// chunk recursion: quad step (barrier + prefetch + wait) every 4th chunk.
// ---------------------------------------------------------------------------
template<int C>
__device__ __forceinline__ void run_chunks(
    uint32_t sb, const uint32_t (&boff)[8], const uint32_t (&ab)[2][8][2],
    const uint32_t* __restrict__ xqg, float (&acc)[2][4][4],
    const uint32_t (&cp_raw)[2], const uint32_t (&cp_dst)[2])
{
    if constexpr (C < kChunks) {
        if constexpr ((C & 3) == 0) {
            __syncthreads();            // buffers of chunks C-4..C-1 reusable
            #pragma unroll
            for (int q = 0; q < 4; q++) {   // exactly 4 commits per quad
                if (C + 4 + q < kChunks)
                    issue_chunk(C + 4 + q, sb, cp_raw, cp_dst);
                CP_COMMIT();
            }
            CP_WAIT4();                 // chunks C..C+3 landed
        }
        uint32_t bb = sb + SM_B + (uint32_t)(C & 7) * kChunkBytes;
        do_kb<C, 0>(bb, boff, ab, xqg, acc);
        do_kb<C, 1>(bb, boff, ab, xqg, acc);
        do_kb<C, 2>(bb, boff, ab, xqg, acc);
        do_kb<C, 3>(bb, boff, ab, xqg, acc);
        run_chunks<C + 1>(sb, boff, ab, xqg, acc, cp_raw, cp_dst);
    }
}

// ---------------------------------------------------------------------------
// main fused kernel: 128-row M-tile per CTA, H=128 as N, 16 warps (4M x 4N),
// 1 CTA per SM, 8 B-buffers, barrier every 4 chunks
// ---------------------------------------------------------------------------
__global__ void __launch_bounds__(kThreads, 1)
rbm_main_kernel(const float* __restrict__ x,
                const float* __restrict__ bias,
                float* __restrict__ out) {
    extern __shared__ char smem_raw[];
    char* sm = (char*)((((uintptr_t)smem_raw) + 1023) & ~(uintptr_t)1023);
    const uint32_t sb = smem_u32(sm);
    const int tid = threadIdx.x;
    const int l   = tid & 31;
    const int w   = tid >> 5;
    const int g   = l >> 2;
    const int t4  = l & 3;
    const int wm  = (w >> 2) * 32;     // warp M offset (0,32,64,96)
    const int wn  = (w & 3) * 32;      // warp N offset (0,32,64,96)
    const int m0  = blockIdx.x * kMTile;

    float*    sbias = (float*)(sm + SM_BIAS);
    float*    spart = (float*)(sm + SM_PART);     // [m][4 wn-groups]
    uint32_t* xq    = (uint32_t*)(sm + SM_XQ);    // [j][32 grp][4 t] u32

    if (tid < kH) sbias[tid] = bias[tid];

    // --- x bf16 tile [m][j], 128B rows, SW128 swizzled (A ldmatrix source);
    //     lives in buffer-4 space, consumed before the first quad barrier ---
    {
        const float4* x4 = (const float4*)(x + (size_t)m0 * kV);
        #pragma unroll
        for (int e = tid; e < kMTile * 16; e += kThreads) {   // 128 rows * 16 f4
            int r = e >> 4, q = e & 15;
            float4 f = x4[e];
            uint32_t u0, u1;
            CVT_BF16X2(u0, f.x, f.y);
            CVT_BF16X2(u1, f.z, f.w);
            uint32_t off = (uint32_t)(r * 128 + q * 8);
            *(uint2*)(sm + SM_XT + SW128(off)) = make_uint2(u0, u1);
        }
    }
    // --- xq[j][grp][t] = bf16x2 broadcast of x[m0 + (grp>>3)*32 + (grp&7) + 8t][j]
    #pragma unroll
    for (int e = tid; e < kV * 32 * 4; e += kThreads) {   // 8192 entries
        int j   = e >> 7;
        int grp = (e >> 2) & 31;
        int t   = e & 3;
        int m   = (grp >> 3) * 32 + (grp & 7) + 8 * t;
        float v = x[(size_t)(m0 + m) * kV + j];
        uint32_t p;
        CVT_BF16X2(p, v, v);
        xq[e] = p;
    }

    // --- cp.async offsets (hoisted): 2 x 16B per thread per chunk ---
    uint32_t cp_raw[2], cp_dst[2];
    #pragma unroll
    for (int p = 0; p < 2; p++) {
        int cg = tid + p * kThreads;
        cp_raw[p] = (uint32_t)((cg >> 3) * 128 + (cg & 7) * 16);
        cp_dst[p] = SW128(cp_raw[p]);
    }

    // prologue: chunks 0..3 into buffers 0..3 (one commit each)
    #pragma unroll
    for (int p = 0; p < 4; p++) { issue_chunk(p, sb, cp_raw, cp_dst); CP_COMMIT(); }

    __syncthreads();   // x tiles + bias ready

    // --- A-base fragments (warp's 32x64 x-tile) in registers, octet-indexed:
    //     ab[mb][jo][0] = row wm+16mb+g,   ab[mb][jo][1] = row +8, octet jo ---
    uint32_t ab[2][8][2];
    {
        int q = l >> 3, rr = l & 7;
        #pragma unroll
        for (int mb = 0; mb < 2; mb++)
        #pragma unroll
        for (int kb = 0; kb < 4; kb++) {
            uint32_t off = (uint32_t)((wm + 16 * mb + (q & 1) * 8 + rr) * 128
                                      + (kb * 16 + (q >> 1) * 8) * 2);
            LDSM_X4(ab[mb][2 * kb][0], ab[mb][2 * kb][1],
                    ab[mb][2 * kb + 1][0], ab[mb][2 * kb + 1][1],
                    sb + SM_XT + SW128(off));
        }
    }

    // --- per-thread B ldmatrix offsets (swizzled, rel. to buffer base) ---
    uint32_t boff[8];
    {
        int q = l >> 3, rr = l & 7;
        #pragma unroll
        for (int kb = 0; kb < 4; kb++)
        #pragma unroll
        for (int nb2 = 0; nb2 < 2; nb2++) {
            uint32_t off = (uint32_t)((wn + nb2 * 16 + (q >> 1) * 8 + rr) * 128
                                      + (kb * 16 + (q & 1) * 8) * 2);
            boff[kb * 2 + nb2] = SW128(off);
        }
    }

    float acc[2][4][4];
    #pragma unroll
    for (int a = 0; a < 2; a++)
    #pragma unroll
    for (int b = 0; b < 4; b++)
    #pragma unroll
    for (int c = 0; c < 4; c++) acc[a][b][c] = 0.0f;

    const int rb0 = wm + g;
    const uint32_t* xqg = xq + ((wm >> 2) + g) * 4;   // grp = (wm>>2)+g

    run_chunks<0>(sb, boff, ab, xqg, acc, cp_raw, cp_dst);

    // --- epilogue: a = bias + 0.5*acc; psi = prod cos(a) ---
    #pragma unroll
    for (int mb = 0; mb < 2; mb++) {
        float p0 = 1.0f, p1 = 1.0f;
        #pragma unroll
        for (int nb = 0; nb < 4; nb++) {
            int col = wn + nb * 8 + 2 * t4;
            #pragma unroll
            for (int cc = 0; cc < 2; cc++) {
                float bv = sbias[col + cc];
                p0 *= cos_poly(bv + 0.5f * acc[mb][nb][cc]);       // row g
                p1 *= cos_poly(bv + 0.5f * acc[mb][nb][2 + cc]);   // row g+8
            }
        }
        p0 *= __shfl_xor_sync(0xFFFFFFFFu, p0, 1);
        p0 *= __shfl_xor_sync(0xFFFFFFFFu, p0, 2);
        p1 *= __shfl_xor_sync(0xFFFFFFFFu, p1, 1);
        p1 *= __shfl_xor_sync(0xFFFFFFFFu, p1, 2);
        if (t4 == 0) {
            spart[(rb0 + 16 * mb) * 4 + (w & 3)]     = p0;
            spart[(rb0 + 16 * mb + 8) * 4 + (w & 3)] = p1;
        }
    }
    __syncthreads();
    if (tid < kMTile) {
        out[m0 + tid] = spart[tid * 4 + 0] * spart[tid * 4 + 1]
                      * spart[tid * 4 + 2] * spart[tid * 4 + 3];
    }
}

// ---------------------------------------------------------------------------
// launch: both kernels request the SAME max dynamic smem -> one carveout.
// ---------------------------------------------------------------------------
extern "C" void kernel_launch(void* const* d_in, const int* in_sizes, int n_in,
                              void* d_out, int out_size) {
    const float* x    = (const float*)d_in[0];   // (16384, 64)
    const float* w1   = (const float*)d_in[1];   // (64, 128)
    const float* w2   = (const float*)d_in[2];   // (128, 64, 64)
    const float* bias = (const float*)d_in[3];   // (128,)
    float* out = (float*)d_out;                  // (16384,)

    cudaFuncSetAttribute(rbm_main_kernel,
                         cudaFuncAttributeMaxDynamicSharedMemorySize, SMEM_TOTAL);
    cudaFuncSetAttribute(prep_kernel,
                         cudaFuncAttributeMaxDynamicSharedMemorySize, SMEM_TOTAL);

    prep_kernel<<<kH, 256, SMEM_TOTAL>>>(w2, w1);   // one CTA per h, same carveout
    rbm_main_kernel<<<16384 / kMTile, kThreads, SMEM_TOTAL>>>(x, bias, out);
}

// round 16
// speedup vs baseline: 1.0536x; 1.0536x over previous
#include <cuda_runtime.h>
#include <cuda_bf16.h>
#include <cstdint>

// ============================================================================
// IsingRBM: psi[m] = prod_h cos(bias[h] + (x@W1)[m,h] + 0.5 * x^T W2[h] x)
// mma.sync.m16n8k16 bf16 (compute_103 baseline PTX; tcgen05 unavailable).
//
// R16 = R11 (best total: fragment-order LDG B, register prefetch, barrier-
// free mainloop, 8-granular packing K=2368 / 37 chunks) split into
// 2 CTAs x 256 threads per SM (M-tile 64, 2M x 4N warps):
//  * two independent CTAs de-phase naturally -> one CTA's LDS->HMUL gaps
//    fill with the other's MMA bursts (R11's single 16-warp CTA stayed
//    phase-correlated; issue was only 21%).
//  * per-thread registers identical to R11 (acc 32 + ab 32 + bfr 32).
//  * smem 27 KB/CTA -> stays in the small-smem regime where the measured
//    total-minus-main gap is ~1-3.5 us (big-smem configs lose ~3 us more).
// ============================================================================

static constexpr int kV = 64;
static constexpr int kH = 128;
static constexpr int kMTile = 64;
static constexpr int kChunks = 37;
static constexpr int kChunkBytes = kH * kV * 2;   // 16384
static constexpr int kThreads = 256;

// smem layout (bytes, relative to 1024-aligned base)
static constexpr int SM_BIAS = 0;                  // 128 f32 = 512
static constexpr int SM_PART = 512;                // 64*4 f32 = 1024
static constexpr int SM_XQ   = 1536;               // 64 j * 16 grp * 4 t u32 = 16384
static constexpr int SM_XT   = 18432;              // 1024-aligned, 8192
static constexpr int SM_END  = SM_XT + 8192;       // 26624
static constexpr int SMEM_TOTAL = SM_END + 1024;   // 27648; x2 CTAs = 55296

// Fragment-ordered B operand: [c][W(4)][kb(4)][q(2)][lane(32)][16B]
__device__ __align__(16) unsigned char g_wb[kChunks * kChunkBytes];

// ---------------------------------------------------------------------------
// schedule: half H (octet of K) -> (row i, j-octet jo).  i == 64 => linear.
// ---------------------------------------------------------------------------
struct HD { int i; int jo; };
__host__ __device__ constexpr HD half_desc(int H) {
    if (H >= 288) return HD{64, H - 288};          // linear term (scale = 1)
    int a = 0, gs = 0;
    while (gs + 8 * (8 - a) <= H) { gs += 8 * (8 - a); ++a; }
    int rem = H - gs, len = 8 - a;
    return HD{8 * a + rem / len, a + rem % len};
}

// ---------------------------------------------------------------------------
// helpers
// ---------------------------------------------------------------------------
__device__ __forceinline__ uint32_t smem_u32(const void* p) {
    uint32_t a;
    asm("{ .reg .u64 t; cvta.to.shared.u64 t, %1; cvt.u32.u64 %0, t; }"
        : "=r"(a) : "l"(p));
    return a;
}

#define SW128(o) ((o) ^ (((o) >> 3) & 0x70))

#define CVT_BF16X2(result, a, b) \
    asm("cvt.rn.bf16x2.f32 %0, %1, %2;" : "=r"(result) : "f"(b), "f"(a))

#define HMUL2(d, a, b) \
    asm("mul.rn.bf16x2 %0, %1, %2;" : "=r"(d) : "r"(a), "r"(b))

#define LDSM_X4(r0, r1, r2, r3, addr) \
    asm volatile("ldmatrix.sync.aligned.m8n8.x4.shared.b16 {%0,%1,%2,%3}, [%4];" \
        : "=r"(r0), "=r"(r1), "=r"(r2), "=r"(r3) : "r"(addr))

#define MMA16816(d, a0, a1, a2, a3, b0, b1) \
    asm volatile("mma.sync.aligned.m16n8k16.row.col.f32.bf16.bf16.f32 " \
        "{%0,%1,%2,%3}, {%4,%5,%6,%7}, {%8,%9}, {%0,%1,%2,%3};" \
        : "+f"((d)[0]), "+f"((d)[1]), "+f"((d)[2]), "+f"((d)[3]) \
        : "r"(a0), "r"(a1), "r"(a2), "r"(a3), "r"(b0), "r"(b1))

__device__ __forceinline__ float cos_poly(float a) {
    // |a| < 0.1 guaranteed by problem statistics; deg-8 Taylor, err < 1e-12
    float t = a * a;
    return 1.0f + t * (-0.5f + t * (4.16666667e-2f +
               t * (-1.38888889e-3f + t * 2.48015873e-5f)));
}

// ---------------------------------------------------------------------------
// prep (verbatim R11, correctness-verified): one CTA per h; stage W2[h] in
// smem; emit folded weights directly in per-thread fragment order.
// h -> W = h>>5 (warp n-group), nb = (h>>3)&3, lrow = h&7.
// uint2 index = c*2048 + kb*128 + t*2 + [W*512 + (nb>>1)*64 + lrow*8 + (nb&1)]
// ---------------------------------------------------------------------------
__global__ void __launch_bounds__(256) prep_kernel(const float* __restrict__ w2,
                                                   const float* __restrict__ w1) {
    __shared__ float sw[4096];
    const int h = blockIdx.x;
    const float4* src = reinterpret_cast<const float4*>(w2 + (size_t)h * 4096);
    #pragma unroll
    for (int e = threadIdx.x; e < 1024; e += 256)
        reinterpret_cast<float4*>(sw)[e] = src[e];
    __syncthreads();

    const int W = h >> 5, nb = (h >> 3) & 3, lrow = h & 7;
    const int hbase = W * 512 + (nb >> 1) * 64 + lrow * 8 + (nb & 1);
    uint2* dst = reinterpret_cast<uint2*>(g_wb);

    // 37 chunks * 4 kb * 4 t = 592 uint2 outputs for this h
    for (int idx = threadIdx.x; idx < kChunks * 16; idx += 256) {
        int c  = idx >> 4;
        int r  = idx & 15;
        int kb = r >> 2;
        int t  = r & 3;
        float v[4];
        #pragma unroll
        for (int q = 0; q < 4; q++) {
            int klocal = (q < 2) ? (2 * t + q) : (2 * t + 6 + q);  // 2t,2t+1,2t+8,2t+9
            HD hd = half_desc(c * 8 + kb * 2 + (klocal >> 3));
            int j = hd.jo * 8 + (klocal & 7);
            if (hd.i == 64)     v[q] = 2.0f * w1[j * kH + h];
            else if (j > hd.i)  v[q] = sw[hd.i * 64 + j] + sw[j * 64 + hd.i];
            else if (j == hd.i) v[q] = sw[hd.i * 64 + j];
            else                v[q] = 0.0f;   // octet padding below diagonal
        }
        uint32_t lo, hi;
        CVT_BF16X2(lo, v[0], v[1]);
        CVT_BF16X2(hi, v[2], v[3]);
        dst[c * 2048 + kb * 128 + t * 2 + hbase] = make_uint2(lo, hi);
    }
}

// ---------------------------------------------------------------------------
// one k16 block (KB) of chunk C: all schedule data compile-time.
// ab[mb][jo][0,1] = bf16x2 of x rows (wm+16mb+g, +8) at j = 8jo + 2*t4.
// xqg: per-thread scale base; j-stride 64 u32 (16-grp layout).
// ---------------------------------------------------------------------------
template<int C, int KB>
__device__ __forceinline__ void do_kb(
    const uint4* __restrict__ gB, uint4 (&bfr)[4][2],
    const uint32_t (&ab)[2][8][2], const uint32_t* __restrict__ xqg,
    float (&acc)[2][4][4])
{
    constexpr HD H0 = half_desc(C * 8 + KB * 2);
    constexpr HD H1 = half_desc(C * 8 + KB * 2 + 1);
    uint32_t sv0[4], sv1[4];
    if constexpr (H0.i == 64) {
        sv0[0] = sv0[1] = sv0[2] = sv0[3] = 0x3F803F80u;    // bf16x2(1,1)
    } else {
        uint4 s = *reinterpret_cast<const uint4*>(xqg + H0.i * 64);
        sv0[0] = s.x; sv0[1] = s.y; sv0[2] = s.z; sv0[3] = s.w;
    }
    if constexpr (H1.i == H0.i) {
        sv1[0] = sv0[0]; sv1[1] = sv0[1]; sv1[2] = sv0[2]; sv1[3] = sv0[3];
    } else if constexpr (H1.i == 64) {
        sv1[0] = sv1[1] = sv1[2] = sv1[3] = 0x3F803F80u;
    } else {
        uint4 s = *reinterpret_cast<const uint4*>(xqg + H1.i * 64);
        sv1[0] = s.x; sv1[1] = s.y; sv1[2] = s.z; sv1[3] = s.w;
    }
    const uint4 lo = bfr[KB][0], hi = bfr[KB][1];
    if constexpr (C + 1 < kChunks) {   // prefetch next chunk's KB fragments
        bfr[KB][0] = gB[(C + 1) * 1024 + KB * 64];
        bfr[KB][1] = gB[(C + 1) * 1024 + KB * 64 + 32];
    }
    #pragma unroll
    for (int mb = 0; mb < 2; mb++) {
        uint32_t t0, t1, t2, t3;
        HMUL2(t0, ab[mb][H0.jo][0], sv0[2 * mb]);      // rows g,   k 0-7
        HMUL2(t1, ab[mb][H0.jo][1], sv0[2 * mb + 1]);  // rows g+8, k 0-7
        HMUL2(t2, ab[mb][H1.jo][0], sv1[2 * mb]);      // rows g,   k 8-15
        HMUL2(t3, ab[mb][H1.jo][1], sv1[2 * mb + 1]);  // rows g+8, k 8-15
        MMA16816(acc[mb][0], t0, t1, t2, t3, lo.x, lo.y);
        MMA16816(acc[mb][1], t0, t1, t2, t3, lo.z, lo.w);
        MMA16816(acc[mb][2], t0, t1, t2, t3, hi.x, hi.y);
        MMA16816(acc[mb][3], t0, t1, t2, t3, hi.z, hi.w);
    }
}

template<int C>
__device__ __forceinline__ void run_chunks(
    const uint4* __restrict__ gB, uint4 (&bfr)[4][2],
    const uint32_t (&ab)[2][8][2], const uint32_t* __restrict__ xqg,
    float (&acc)[2][4][4])
{
    if constexpr (C < kChunks) {
        do_kb<C, 0>(gB, bfr, ab, xqg, acc);
        do_kb<C, 1>(gB, bfr, ab, xqg, acc);
        do_kb<C, 2>(gB, bfr, ab, xqg, acc);
        do_kb<C, 3>(gB, bfr, ab, xqg, acc);
        run_chunks<C + 1>(gB, bfr, ab, xqg, acc);
    }
}

// ---------------------------------------------------------------------------
// main fused kernel: 64-row M-tile per CTA, H=128 as N, 8 warps (2M x 4N),
// 2 CTAs per SM, NO barriers in the main loop
// ---------------------------------------------------------------------------
__global__ void __launch_bounds__(kThreads, 2)
rbm_main_kernel(const float* __restrict__ x,
                const float* __restrict__ bias,
                float* __restrict__ out) {
    extern __shared__ char smem_raw[];
    char* sm = (char*)((((uintptr_t)smem_raw) + 1023) & ~(uintptr_t)1023);
    const uint32_t sb = smem_u32(sm);
    const int tid = threadIdx.x;
    const int l   = tid & 31;
    const int w   = tid >> 5;
    const int g   = l >> 2;
    const int t4  = l & 3;
    const int wm  = (w >> 2) * 32;     // warp M offset (0,32)
    const int wn  = (w & 3) * 32;      // warp N offset (0,32,64,96)
    const int m0  = blockIdx.x * kMTile;

    float*    sbias = (float*)(sm + SM_BIAS);
    float*    spart = (float*)(sm + SM_PART);     // [m][4 wn-groups]
    uint32_t* xq    = (uint32_t*)(sm + SM_XQ);    // [j][16 grp][4 t] u32

    if (tid < kH) sbias[tid] = bias[tid];

    // --- x bf16 tile [m][j], 128B rows, SW128 swizzled (A ldmatrix source) ---
    {
        const float4* x4 = (const float4*)(x + (size_t)m0 * kV);
        #pragma unroll
        for (int e = tid; e < kMTile * 16; e += kThreads) {   // 64 rows * 16 f4
            int r = e >> 4, q = e & 15;
            float4 f = x4[e];
            uint32_t u0, u1;
            CVT_BF16X2(u0, f.x, f.y);
            CVT_BF16X2(u1, f.z, f.w);
            uint32_t off = (uint32_t)(r * 128 + q * 8);
            *(uint2*)(sm + SM_XT + SW128(off)) = make_uint2(u0, u1);
        }
    }
    // --- xq[j][grp][t] = bf16x2 broadcast of x[m0 + (grp>>3)*32 + (grp&7) + 8t][j]
    #pragma unroll
    for (int e = tid; e < kV * 16 * 4; e += kThreads) {   // 4096 entries
        int j   = e >> 6;
        int grp = (e >> 2) & 15;
        int t   = e & 3;
        int m   = (grp >> 3) * 32 + (grp & 7) + 8 * t;
        float v = x[(size_t)(m0 + m) * kV + j];
        uint32_t p;
        CVT_BF16X2(p, v, v);
        xq[e] = p;
    }

    // --- per-thread fragment pointer into g_wb (uint4 units) ---
    const uint4* gB = reinterpret_cast<const uint4*>(g_wb) + (w & 3) * 256 + l;

    // --- prologue: chunk 0 fragments into registers (gmem; no smem dep) ---
    uint4 bfr[4][2];
    #pragma unroll
    for (int kb = 0; kb < 4; kb++) {
        bfr[kb][0] = gB[kb * 64];
        bfr[kb][1] = gB[kb * 64 + 32];
    }

    __syncthreads();   // x tiles + bias ready (only barrier before epilogue)

    // --- A-base fragments (warp's 32x64 x-tile) in registers, octet-indexed ---
    uint32_t ab[2][8][2];
    {
        int q = l >> 3, rr = l & 7;
        #pragma unroll
        for (int mb = 0; mb < 2; mb++)
        #pragma unroll
        for (int kb = 0; kb < 4; kb++) {
            uint32_t off = (uint32_t)((wm + 16 * mb + (q & 1) * 8 + rr) * 128
                                      + (kb * 16 + (q >> 1) * 8) * 2);
            LDSM_X4(ab[mb][2 * kb][0], ab[mb][2 * kb][1],
                    ab[mb][2 * kb + 1][0], ab[mb][2 * kb + 1][1],
                    sb + SM_XT + SW128(off));
        }
    }

    float acc[2][4][4];
    #pragma unroll
    for (int a = 0; a < 2; a++)
    #pragma unroll
    for (int b = 0; b < 4; b++)
    #pragma unroll
    for (int c = 0; c < 4; c++) acc[a][b][c] = 0.0f;

    const int rb0 = wm + g;
    const uint32_t* xqg = xq + ((wm >> 2) + g) * 4;   // grp = (wm>>2)+g

    run_chunks<0>(gB, bfr, ab, xqg, acc);

    // --- epilogue: a = bias + 0.5*acc; psi = prod cos(a) ---
    #pragma unroll
    for (int mb = 0; mb < 2; mb++) {
        float p0 = 1.0f, p1 = 1.0f;
        #pragma unroll
        for (int nb = 0; nb < 4; nb++) {
            int col = wn + nb * 8 + 2 * t4;
            #pragma unroll
            for (int cc = 0; cc < 2; cc++) {
                float bv = sbias[col + cc];
                p0 *= cos_poly(bv + 0.5f * acc[mb][nb][cc]);       // row g
                p1 *= cos_poly(bv + 0.5f * acc[mb][nb][2 + cc]);   // row g+8
            }
        }
        p0 *= __shfl_xor_sync(0xFFFFFFFFu, p0, 1);
        p0 *= __shfl_xor_sync(0xFFFFFFFFu, p0, 2);
        p1 *= __shfl_xor_sync(0xFFFFFFFFu, p1, 1);
        p1 *= __shfl_xor_sync(0xFFFFFFFFu, p1, 2);
        if (t4 == 0) {
            spart[(rb0 + 16 * mb) * 4 + (w & 3)]     = p0;
            spart[(rb0 + 16 * mb + 8) * 4 + (w & 3)] = p1;
        }
    }
    __syncthreads();
    if (tid < kMTile) {
        out[m0 + tid] = spart[tid * 4 + 0] * spart[tid * 4 + 1]
                      * spart[tid * 4 + 2] * spart[tid * 4 + 3];
    }
}

// ---------------------------------------------------------------------------
// launch
// ---------------------------------------------------------------------------
extern "C" void kernel_launch(void* const* d_in, const int* in_sizes, int n_in,
                              void* d_out, int out_size) {
    const float* x    = (const float*)d_in[0];   // (16384, 64)
    const float* w1   = (const float*)d_in[1];   // (64, 128)
    const float* w2   = (const float*)d_in[2];   // (128, 64, 64)
    const float* bias = (const float*)d_in[3];   // (128,)
    float* out = (float*)d_out;                  // (16384,)

    cudaFuncSetAttribute(rbm_main_kernel,
                         cudaFuncAttributeMaxDynamicSharedMemorySize, SMEM_TOTAL);

    prep_kernel<<<kH, 256>>>(w2, w1);            // one CTA per h
    rbm_main_kernel<<<16384 / kMTile, kThreads, SMEM_TOTAL>>>(x, bias, out);
}

// round 17
// speedup vs baseline: 1.1325x; 1.0750x over previous
#include <cuda_runtime.h>
#include <cuda_bf16.h>
#include <cstdint>

// ============================================================================
// IsingRBM: psi[m] = prod_h cos(bias[h] + (x@W1)[m,h] + 0.5 * x^T W2[h] x)
// mma.sync.m16n8k16 bf16 (compute_103 baseline PTX; tcgen05 unavailable).
//
// R17 = R16 (best main: fragment-order LDG B, register prefetch, barrier-free
// mainloop, 8-granular packing K=2368 / 37 chunks, 2 CTAs x 256 thr / SM)
// with the prologue fixed: the xq scale table is now built FROM SMEM (XT,
// bf16) via LDS.u16 + duplicate instead of 4096 column-strided scalar LDGs
// per CTA (one 32B sector per lane, L2-latency exposed, uncovered by MMAs).
// Bit-identical arithmetic: XT's bf16 rounding == CVT_BF16X2(v,v).
// ============================================================================

static constexpr int kV = 64;
static constexpr int kH = 128;
static constexpr int kMTile = 64;
static constexpr int kChunks = 37;
static constexpr int kChunkBytes = kH * kV * 2;   // 16384
static constexpr int kThreads = 256;

// smem layout (bytes, relative to 1024-aligned base)
static constexpr int SM_BIAS = 0;                  // 128 f32 = 512
static constexpr int SM_PART = 512;                // 64*4 f32 = 1024
static constexpr int SM_XQ   = 1536;               // 64 j * 16 grp * 4 t u32 = 16384
static constexpr int SM_XT   = 18432;              // 1024-aligned, 8192
static constexpr int SM_END  = SM_XT + 8192;       // 26624
static constexpr int SMEM_TOTAL = SM_END + 1024;   // 27648; x2 CTAs = 55296

// Fragment-ordered B operand: [c][W(4)][kb(4)][q(2)][lane(32)][16B]
__device__ __align__(16) unsigned char g_wb[kChunks * kChunkBytes];

// ---------------------------------------------------------------------------
// schedule: half H (octet of K) -> (row i, j-octet jo).  i == 64 => linear.
// ---------------------------------------------------------------------------
struct HD { int i; int jo; };
__host__ __device__ constexpr HD half_desc(int H) {
    if (H >= 288) return HD{64, H - 288};          // linear term (scale = 1)
    int a = 0, gs = 0;
    while (gs + 8 * (8 - a) <= H) { gs += 8 * (8 - a); ++a; }
    int rem = H - gs, len = 8 - a;
    return HD{8 * a + rem / len, a + rem % len};
}

// ---------------------------------------------------------------------------
// helpers
// ---------------------------------------------------------------------------
__device__ __forceinline__ uint32_t smem_u32(const void* p) {
    uint32_t a;
    asm("{ .reg .u64 t; cvta.to.shared.u64 t, %1; cvt.u32.u64 %0, t; }"
        : "=r"(a) : "l"(p));
    return a;
}

#define SW128(o) ((o) ^ (((o) >> 3) & 0x70))

#define CVT_BF16X2(result, a, b) \
    asm("cvt.rn.bf16x2.f32 %0, %1, %2;" : "=r"(result) : "f"(b), "f"(a))

#define HMUL2(d, a, b) \
    asm("mul.rn.bf16x2 %0, %1, %2;" : "=r"(d) : "r"(a), "r"(b))

#define LDSM_X4(r0, r1, r2, r3, addr) \
    asm volatile("ldmatrix.sync.aligned.m8n8.x4.shared.b16 {%0,%1,%2,%3}, [%4];" \
        : "=r"(r0), "=r"(r1), "=r"(r2), "=r"(r3) : "r"(addr))

#define MMA16816(d, a0, a1, a2, a3, b0, b1) \
    asm volatile("mma.sync.aligned.m16n8k16.row.col.f32.bf16.bf16.f32 " \
        "{%0,%1,%2,%3}, {%4,%5,%6,%7}, {%8,%9}, {%0,%1,%2,%3};" \
        : "+f"((d)[0]), "+f"((d)[1]), "+f"((d)[2]), "+f"((d)[3]) \
        : "r"(a0), "r"(a1), "r"(a2), "r"(a3), "r"(b0), "r"(b1))

__device__ __forceinline__ float cos_poly(float a) {
    // |a| < 0.1 guaranteed by problem statistics; deg-8 Taylor, err < 1e-12
    float t = a * a;
    return 1.0f + t * (-0.5f + t * (4.16666667e-2f +
               t * (-1.38888889e-3f + t * 2.48015873e-5f)));
}

// ---------------------------------------------------------------------------
// prep (verbatim R11/R16, correctness-verified): one CTA per h; stage W2[h]
// in smem; emit folded weights directly in per-thread fragment order.
// h -> W = h>>5 (warp n-group), nb = (h>>3)&3, lrow = h&7.
// uint2 index = c*2048 + kb*128 + t*2 + [W*512 + (nb>>1)*64 + lrow*8 + (nb&1)]
// ---------------------------------------------------------------------------
__global__ void __launch_bounds__(256) prep_kernel(const float* __restrict__ w2,
                                                   const float* __restrict__ w1) {
    __shared__ float sw[4096];
    const int h = blockIdx.x;
    const float4* src = reinterpret_cast<const float4*>(w2 + (size_t)h * 4096);
    #pragma unroll
    for (int e = threadIdx.x; e < 1024; e += 256)
        reinterpret_cast<float4*>(sw)[e] = src[e];
    __syncthreads();

    const int W = h >> 5, nb = (h >> 3) & 3, lrow = h & 7;
    const int hbase = W * 512 + (nb >> 1) * 64 + lrow * 8 + (nb & 1);
    uint2* dst = reinterpret_cast<uint2*>(g_wb);

    // 37 chunks * 4 kb * 4 t = 592 uint2 outputs for this h
    for (int idx = threadIdx.x; idx < kChunks * 16; idx += 256) {
        int c  = idx >> 4;
        int r  = idx & 15;
        int kb = r >> 2;
        int t  = r & 3;
        float v[4];
        #pragma unroll
        for (int q = 0; q < 4; q++) {
            int klocal = (q < 2) ? (2 * t + q) : (2 * t + 6 + q);  // 2t,2t+1,2t+8,2t+9
            HD hd = half_desc(c * 8 + kb * 2 + (klocal >> 3));
            int j = hd.jo * 8 + (klocal & 7);
            if (hd.i == 64)     v[q] = 2.0f * w1[j * kH + h];
            else if (j > hd.i)  v[q] = sw[hd.i * 64 + j] + sw[j * 64 + hd.i];
            else if (j == hd.i) v[q] = sw[hd.i * 64 + j];
            else                v[q] = 0.0f;   // octet padding below diagonal
        }
        uint32_t lo, hi;
        CVT_BF16X2(lo, v[0], v[1]);
        CVT_BF16X2(hi, v[2], v[3]);
        dst[c * 2048 + kb * 128 + t * 2 + hbase] = make_uint2(lo, hi);
    }
}

// ---------------------------------------------------------------------------
// one k16 block (KB) of chunk C: all schedule data compile-time.
// ab[mb][jo][0,1] = bf16x2 of x rows (wm+16mb+g, +8) at j = 8jo + 2*t4.
// xqg: per-thread scale base; j-stride 64 u32 (16-grp layout).
// ---------------------------------------------------------------------------
template<int C, int KB>
__device__ __forceinline__ void do_kb(
    const uint4* __restrict__ gB, uint4 (&bfr)[4][2],
    const uint32_t (&ab)[2][8][2], const uint32_t* __restrict__ xqg,
    float (&acc)[2][4][4])
{
    constexpr HD H0 = half_desc(C * 8 + KB * 2);
    constexpr HD H1 = half_desc(C * 8 + KB * 2 + 1);
    uint32_t sv0[4], sv1[4];
    if constexpr (H0.i == 64) {
        sv0[0] = sv0[1] = sv0[2] = sv0[3] = 0x3F803F80u;    // bf16x2(1,1)
    } else {
        uint4 s = *reinterpret_cast<const uint4*>(xqg + H0.i * 64);
        sv0[0] = s.x; sv0[1] = s.y; sv0[2] = s.z; sv0[3] = s.w;
    }
    if constexpr (H1.i == H0.i) {
        sv1[0] = sv0[0]; sv1[1] = sv0[1]; sv1[2] = sv0[2]; sv1[3] = sv0[3];
    } else if constexpr (H1.i == 64) {
        sv1[0] = sv1[1] = sv1[2] = sv1[3] = 0x3F803F80u;
    } else {
        uint4 s = *reinterpret_cast<const uint4*>(xqg + H1.i * 64);
        sv1[0] = s.x; sv1[1] = s.y; sv1[2] = s.z; sv1[3] = s.w;
    }
    const uint4 lo = bfr[KB][0], hi = bfr[KB][1];
    if constexpr (C + 1 < kChunks) {   // prefetch next chunk's KB fragments
        bfr[KB][0] = gB[(C + 1) * 1024 + KB * 64];
        bfr[KB][1] = gB[(C + 1) * 1024 + KB * 64 + 32];
    }
    #pragma unroll
    for (int mb = 0; mb < 2; mb++) {
        uint32_t t0, t1, t2, t3;
        HMUL2(t0, ab[mb][H0.jo][0], sv0[2 * mb]);      // rows g,   k 0-7
        HMUL2(t1, ab[mb][H0.jo][1], sv0[2 * mb + 1]);  // rows g+8, k 0-7
        HMUL2(t2, ab[mb][H1.jo][0], sv1[2 * mb]);      // rows g,   k 8-15
        HMUL2(t3, ab[mb][H1.jo][1], sv1[2 * mb + 1]);  // rows g+8, k 8-15
        MMA16816(acc[mb][0], t0, t1, t2, t3, lo.x, lo.y);
        MMA16816(acc[mb][1], t0, t1, t2, t3, lo.z, lo.w);
        MMA16816(acc[mb][2], t0, t1, t2, t3, hi.x, hi.y);
        MMA16816(acc[mb][3], t0, t1, t2, t3, hi.z, hi.w);
    }
}

template<int C>
__device__ __forceinline__ void run_chunks(
    const uint4* __restrict__ gB, uint4 (&bfr)[4][2],
    const uint32_t (&ab)[2][8][2], const uint32_t* __restrict__ xqg,
    float (&acc)[2][4][4])
{
    if constexpr (C < kChunks) {
        do_kb<C, 0>(gB, bfr, ab, xqg, acc);
        do_kb<C, 1>(gB, bfr, ab, xqg, acc);
        do_kb<C, 2>(gB, bfr, ab, xqg, acc);
        do_kb<C, 3>(gB, bfr, ab, xqg, acc);
        run_chunks<C + 1>(gB, bfr, ab, xqg, acc);
    }
}

// ---------------------------------------------------------------------------
// main fused kernel: 64-row M-tile per CTA, H=128 as N, 8 warps (2M x 4N),
// 2 CTAs per SM, NO barriers in the main loop
// ---------------------------------------------------------------------------
__global__ void __launch_bounds__(kThreads, 2)
rbm_main_kernel(const float* __restrict__ x,
                const float* __restrict__ bias,
                float* __restrict__ out) {
    extern __shared__ char smem_raw[];
    char* sm = (char*)((((uintptr_t)smem_raw) + 1023) & ~(uintptr_t)1023);
    const uint32_t sb = smem_u32(sm);
    const int tid = threadIdx.x;
    const int l   = tid & 31;
    const int w   = tid >> 5;
    const int g   = l >> 2;
    const int t4  = l & 3;
    const int wm  = (w >> 2) * 32;     // warp M offset (0,32)
    const int wn  = (w & 3) * 32;      // warp N offset (0,32,64,96)
    const int m0  = blockIdx.x * kMTile;

    float*    sbias = (float*)(sm + SM_BIAS);
    float*    spart = (float*)(sm + SM_PART);     // [m][4 wn-groups]
    uint32_t* xq    = (uint32_t*)(sm + SM_XQ);    // [j][16 grp][4 t] u32

    if (tid < kH) sbias[tid] = bias[tid];

    // --- x bf16 tile [m][j], 128B rows, SW128 swizzled (coalesced LDG.128) ---
    {
        const float4* x4 = (const float4*)(x + (size_t)m0 * kV);
        #pragma unroll
        for (int e = tid; e < kMTile * 16; e += kThreads) {   // 64 rows * 16 f4
            int r = e >> 4, q = e & 15;
            float4 f = x4[e];
            uint32_t u0, u1;
            CVT_BF16X2(u0, f.x, f.y);
            CVT_BF16X2(u1, f.z, f.w);
            uint32_t off = (uint32_t)(r * 128 + q * 8);
            *(uint2*)(sm + SM_XT + SW128(off)) = make_uint2(u0, u1);
        }
    }

    // --- per-thread fragment pointer into g_wb (uint4 units) ---
    const uint4* gB = reinterpret_cast<const uint4*>(g_wb) + (w & 3) * 256 + l;

    // --- prologue: chunk 0 fragments into registers (gmem; no smem dep) ---
    uint4 bfr[4][2];
    #pragma unroll
    for (int kb = 0; kb < 4; kb++) {
        bfr[kb][0] = gB[kb * 64];
        bfr[kb][1] = gB[kb * 64 + 32];
    }

    __syncthreads();   // XT + bias ready

    // --- xq[j][grp][t] built FROM XT (smem), no scattered gmem loads:
    //     value = bf16x2 dup of XT[m][j], m = (grp>>3)*32 + (grp&7) + 8t ---
    #pragma unroll
    for (int e = tid; e < kV * 16 * 4; e += kThreads) {   // 4096 entries
        int j   = e >> 6;
        int grp = (e >> 2) & 15;
        int t   = e & 3;
        int m   = (grp >> 3) * 32 + (grp & 7) + 8 * t;
        uint32_t off = SW128((uint32_t)(m * 128 + j * 2));
        uint32_t b16;
        asm volatile("ld.shared.u16 %0, [%1];"
                     : "=r"(b16) : "r"(sb + SM_XT + off));
        xq[e] = b16 | (b16 << 16);
    }

    // --- A-base fragments (warp's 32x64 x-tile) in registers, octet-indexed ---
    uint32_t ab[2][8][2];
    {
        int q = l >> 3, rr = l & 7;
        #pragma unroll
        for (int mb = 0; mb < 2; mb++)
        #pragma unroll
        for (int kb = 0; kb < 4; kb++) {
            uint32_t off = (uint32_t)((wm + 16 * mb + (q & 1) * 8 + rr) * 128
                                      + (kb * 16 + (q >> 1) * 8) * 2);
            LDSM_X4(ab[mb][2 * kb][0], ab[mb][2 * kb][1],
                    ab[mb][2 * kb + 1][0], ab[mb][2 * kb + 1][1],
                    sb + SM_XT + SW128(off));
        }
    }

    __syncthreads();   // xq complete (threads read other threads' entries)

    float acc[2][4][4];
    #pragma unroll
    for (int a = 0; a < 2; a++)
    #pragma unroll
    for (int b = 0; b < 4; b++)
    #pragma unroll
    for (int c = 0; c < 4; c++) acc[a][b][c] = 0.0f;

    const int rb0 = wm + g;
    const uint32_t* xqg = xq + ((wm >> 2) + g) * 4;   // grp = (wm>>2)+g

    run_chunks<0>(gB, bfr, ab, xqg, acc);

    // --- epilogue: a = bias + 0.5*acc; psi = prod cos(a) ---
    #pragma unroll
    for (int mb = 0; mb < 2; mb++) {
        float p0 = 1.0f, p1 = 1.0f;
        #pragma unroll
        for (int nb = 0; nb < 4; nb++) {
            int col = wn + nb * 8 + 2 * t4;
            #pragma unroll
            for (int cc = 0; cc < 2; cc++) {
                float bv = sbias[col + cc];
                p0 *= cos_poly(bv + 0.5f * acc[mb][nb][cc]);       // row g
                p1 *= cos_poly(bv + 0.5f * acc[mb][nb][2 + cc]);   // row g+8
            }
        }
        p0 *= __shfl_xor_sync(0xFFFFFFFFu, p0, 1);
        p0 *= __shfl_xor_sync(0xFFFFFFFFu, p0, 2);
        p1 *= __shfl_xor_sync(0xFFFFFFFFu, p1, 1);
        p1 *= __shfl_xor_sync(0xFFFFFFFFu, p1, 2);
        if (t4 == 0) {
            spart[(rb0 + 16 * mb) * 4 + (w & 3)]     = p0;
            spart[(rb0 + 16 * mb + 8) * 4 + (w & 3)] = p1;
        }
    }
    __syncthreads();
    if (tid < kMTile) {
        out[m0 + tid] = spart[tid * 4 + 0] * spart[tid * 4 + 1]
                      * spart[tid * 4 + 2] * spart[tid * 4 + 3];
    }
}

// ---------------------------------------------------------------------------
// launch
// ---------------------------------------------------------------------------
extern "C" void kernel_launch(void* const* d_in, const int* in_sizes, int n_in,
                              void* d_out, int out_size) {
    const float* x    = (const float*)d_in[0];   // (16384, 64)
    const float* w1   = (const float*)d_in[1];   // (64, 128)
    const float* w2   = (const float*)d_in[2];   // (128, 64, 64)
    const float* bias = (const float*)d_in[3];   // (128,)
    float* out = (float*)d_out;                  // (16384,)

    cudaFuncSetAttribute(rbm_main_kernel,
                         cudaFuncAttributeMaxDynamicSharedMemorySize, SMEM_TOTAL);

    prep_kernel<<<kH, 256>>>(w2, w1);            // one CTA per h
    rbm_main_kernel<<<16384 / kMTile, kThreads, SMEM_TOTAL>>>(x, bias, out);
}